// round 14
// baseline (speedup 1.0000x reference)
#include <cuda_runtime.h>
#include <cstdint>

#define NN 4
#define PP 128
#define HH 64
#define UU 64
#define BB 15
#define FAVG 49.0f
#define NPG 32   // p-groups for colsum partials (4 p's each)

// ---------------- device scratch ----------------
__device__ float g_rows[NN*HH*PP];
__device__ float g_diag[NN*HH*PP];
__device__ float g_cpart[NPG*NN*PP*HH];
__device__ float g_Fq[NN*PP*UU];
__device__ float g_Fp[NN*PP*UU];
__device__ float g_Fd[NN*PP*UU];

// ---------------- pass 1 (fused): single x read -> rows, diag, colsum partials ----------------
__global__ void __launch_bounds__(256)
fuse_kernel(const float* __restrict__ x, const float* __restrict__ npart) {
    const int pg = blockIdx.x;
    const int n  = blockIdx.y;
    const int p0 = pg * 4;
    const int t  = threadIdx.x;
    const int h4 = t & 15;
    const int qg = t >> 4;

    __shared__ float4 spart[16][4][16];

    const float4* x4 = (const float4*)x;
    const float inv = 1.0f / npart[n];

    float4 col[8];
    #pragma unroll
    for (int j = 0; j < 8; ++j) col[j] = make_float4(0.f, 0.f, 0.f, 0.f);

    #pragma unroll
    for (int p = 0; p < 4; ++p) {
        float4 rp = make_float4(0.f, 0.f, 0.f, 0.f);
        const size_t base = ((size_t)(n * PP + p0 + p)) * PP * 16;
        #pragma unroll
        for (int j = 0; j < 8; ++j) {
            const int q = qg + j * 16;
            const float4 v = x4[base + q * 16 + h4];
            col[j].x += v.x; col[j].y += v.y; col[j].z += v.z; col[j].w += v.w;
            rp.x += v.x; rp.y += v.y; rp.z += v.z; rp.w += v.w;
        }
        spart[qg][p][h4] = rp;
    }
    {
        float4* cp = (float4*)g_cpart + ((size_t)(pg * NN + n)) * PP * 16;
        #pragma unroll
        for (int j = 0; j < 8; ++j)
            cp[(qg + j * 16) * 16 + h4] = col[j];
    }
    __syncthreads();
    if (t < 64) {
        const int p   = t >> 4;
        const int hh4 = t & 15;
        float4 r = spart[0][p][hh4];
        #pragma unroll
        for (int g = 1; g < 16; ++g) {
            const float4 v = spart[g][p][hh4];
            r.x += v.x; r.y += v.y; r.z += v.z; r.w += v.w;
        }
        const int P = p0 + p;
        const int gb = (n * HH + hh4 * 4) * PP + P;
        g_rows[gb + 0*PP] = r.x * inv;
        g_rows[gb + 1*PP] = r.y * inv;
        g_rows[gb + 2*PP] = r.z * inv;
        g_rows[gb + 3*PP] = r.w * inv;
        const float4 d = x4[(((size_t)(n * PP + P)) * PP + P) * 16 + hh4];
        g_diag[gb + 0*PP] = d.x;
        g_diag[gb + 1*PP] = d.y;
        g_diag[gb + 2*PP] = d.z;
        g_diag[gb + 3*PP] = d.w;
    }
}

// ---------------- pass 2 (fused): scalars + coefficients + field GEMMs ----------------
__global__ void __launch_bounds__(256)
pro_kernel(const float* __restrict__ npart,
           const float* __restrict__ alpha0,
           const float* __restrict__ c00,
           const float* __restrict__ c01,
           const float* __restrict__ c10,
           const float* __restrict__ c11,
           const float* __restrict__ bias,
           const float* __restrict__ dbias) {
    const int n  = blockIdx.y;
    const int i0 = blockIdx.x * 4;
    const int tid = threadIdx.x;

    __shared__ float sRR[HH * UU];
    __shared__ float sD[HH][4], sC[HH][4], sR[HH][4];
    __shared__ float sSD[HH], sSA[HH];
    __shared__ float sM[HH][10];
    __shared__ float sA[HH][16];

    const float np  = npart[n];
    const float inv = 1.0f / np;

    #pragma unroll
    for (int it = 0; it < 16; ++it) {
        const int idx = tid + it * 256;
        sRR[idx] = c10[idx] * c11[idx];
    }
    {
        const int hh = tid >> 2;
        const int ii = tid & 3;
        const int gi = (n * HH + hh) * PP + i0 + ii;
        sD[hh][ii] = g_diag[gi];
        sR[hh][ii] = g_rows[gi];
    }
    {
        const int hh = tid & 63;
        const int ii = tid >> 6;
        const float* cp = g_cpart + ((size_t)n * PP + i0 + ii) * HH + hh;
        float s = 0.0f;
        #pragma unroll 8
        for (int g = 0; g < NPG; ++g)
            s += cp[(size_t)g * (NN * PP * HH)];
        sC[hh][ii] = s * inv;
    }
    {
        const int w = tid >> 5, lane = tid & 31;
        #pragma unroll
        for (int j = 0; j < 8; ++j) {
            const int h = w * 8 + j;
            const int base = (n * HH + h) * PP;
            float d = g_diag[base + lane] + g_diag[base + lane + 32]
                    + g_diag[base + lane + 64] + g_diag[base + lane + 96];
            float r = g_rows[base + lane] + g_rows[base + lane + 32]
                    + g_rows[base + lane + 64] + g_rows[base + lane + 96];
            #pragma unroll
            for (int o = 16; o > 0; o >>= 1) {
                d += __shfl_down_sync(0xffffffffu, d, o);
                r += __shfl_down_sync(0xffffffffu, r, o);
            }
            if (lane == 0) { sSD[h] = d * inv; sSA[h] = r * inv; }
        }
    }
    {
        const float ratio = np / FAVG;
        for (int idx = tid; idx < HH * 10; idx += 256)
            sM[idx / 10][idx % 10] = powf(ratio, alpha0[idx]);
    }
    for (int idx = tid; idx < HH * BB; idx += 256)
        sA[idx / BB][idx % BB] = c00[idx];
    __syncthreads();

    const int u  = tid & 63;
    const int ii = tid >> 6;

    float cb[BB];
    #pragma unroll
    for (int b = 2; b < BB; ++b) cb[b] = c01[b * UU + u];

    float aq = 0.0f, ap = 0.0f, ad = 0.0f, vp = 0.0f, vd = 0.0f;

    #pragma unroll 4
    for (int h = 0; h < HH; ++h) {
        const float r = sRR[h * UU + u];
        const float* a = sA[h];
        const float* m = sM[h];
        const float d  = sD[h][ii];
        const float cl = sC[h][ii];
        const float rw = sR[h][ii];
        aq += (a[2]  * cb[2]  * r)        * d
            + (a[5]  * cb[5]  * r * m[0]) * cl
            + (a[6]  * cb[6]  * r * m[1]) * rw;
        ap += (a[3]  * cb[3]  * r)        * d
            + (a[8]  * cb[8]  * r * m[3]) * cl
            + (a[9]  * cb[9]  * r * m[4]) * rw;
        ad += (a[4]  * cb[4]  * r)        * d
            + (a[12] * cb[12] * r * m[7]) * cl
            + (a[11] * cb[11] * r * m[6]) * rw;
        vp += (a[7]  * cb[7]  * r * m[2]) * sSD[h]
            + (a[13] * cb[13] * r * m[8]) * sSA[h];
        vd += (a[10] * cb[10] * r * m[5]) * sSD[h]
            + (a[14] * cb[14] * r * m[9]) * sSA[h];
    }

    const int i = i0 + ii;
    g_Fq[(n * PP + i) * UU + u] = aq + bias[u];
    g_Fp[(n * PP + i) * UU + u] = ap + vp;
    g_Fd[(n * PP + i) * UU + u] = ad + vd + dbias[u];
}

// ---------------- main: tf32 GEMM, fragment-packed smem, term-major MMA order ----------------
// sAr/sAe: [mb=8][kk=8][lane=32] float4 {a0,a1,a2,a3}
// sB:      [kk=8][nb=8][lane=32] float4 {br0,br1,be0,be1}
constexpr int A_FRAGS = 8 * 8 * 32;                       // float4 count
constexpr int SMEM_FLOATS = 3 * A_FRAGS * 4 + 128;        // 24704 floats = 96.5KB

#define CVT_TF32(r, f) asm("cvt.rna.tf32.f32 %0, %1;" : "=r"(r) : "f"(f))
#define MMA_TF32(d, a0_, a1_, a2_, a3_, b0_, b1_) \
    asm volatile("mma.sync.aligned.m16n8k8.row.col.f32.tf32.tf32.f32 " \
        "{%0,%1,%2,%3},{%4,%5,%6,%7},{%8,%9},{%0,%1,%2,%3};" \
        : "+f"(d[0]), "+f"(d[1]), "+f"(d[2]), "+f"(d[3]) \
        : "r"(a0_), "r"(a1_), "r"(a2_), "r"(a3_), "r"(b0_), "r"(b1_))

__global__ void __launch_bounds__(256, 2)
main_kernel(const float* __restrict__ x,
            const unsigned int* __restrict__ mask,
            const float* __restrict__ c00,
            const float* __restrict__ c01,
            const float* __restrict__ c10,
            const float* __restrict__ c11,
            float* __restrict__ out) {
    extern __shared__ float sm[];
    float* sAr = sm;                      // A_FRAGS float4
    float* sAe = sAr + A_FRAGS * 4;
    float* sB  = sAe + A_FRAGS * 4;
    float* sFp = sB + A_FRAGS * 4;        // [64]
    float* sFd = sFp + 64;                // [64]

    const int p = blockIdx.x;
    const int n = blockIdx.y;
    const int tid = threadIdx.x;
    const int lane = tid & 31;
    const int w = tid >> 5;
    const int mw = w & 3;                 // 4 m-warps
    const int nw = w >> 2;                // 2 n-warps
    const int g = lane >> 2;
    const int c = lane & 3;
    const int m0 = mw * 32;
    const int n0 = nw * 32;

    if (tid < 64) {
        sFp[tid] = g_Fp[(n * PP + p) * UU + tid];
        sFd[tid] = g_Fd[(n * PP + p) * UU + tid];
    }

    float acc[2][4][4];
    #pragma unroll
    for (int mt = 0; mt < 2; ++mt)
        #pragma unroll
        for (int nt = 0; nt < 4; ++nt)
            #pragma unroll
            for (int j = 0; j < 4; ++j) acc[mt][nt][j] = 0.0f;

    #pragma unroll 1
    for (int pass = 0; pass < 2; ++pass) {
        if (pass > 0) __syncthreads();

        // ---- stage X (direct / transposed) into fragment layout, split tf32 ----
        #pragma unroll
        for (int it = 0; it < 8; ++it) {
            float f[4];
            int row, h0;
            if (pass == 0) {
                const int idx4 = tid + it * 256;
                const float4 v = ((const float4*)(x + ((size_t)(n * PP + p)) * PP * HH))[idx4];
                row = idx4 >> 4;
                h0  = (idx4 & 15) << 2;
                f[0] = v.x; f[1] = v.y; f[2] = v.z; f[3] = v.w;
            } else {
                row = (tid >> 4) + it * 16;
                h0  = (tid & 15) << 2;
                const float4 v = *(const float4*)(x + (((size_t)(n * PP + row)) * PP + p) * HH + h0);
                f[0] = v.x; f[1] = v.y; f[2] = v.z; f[3] = v.w;
            }
            const int mb  = row >> 4;
            const int rt  = row & 15;
            const int ga  = rt & 7;
            const int rhi = rt >> 3;
            const int kk  = h0 >> 3;
            const int khi = (h0 >> 2) & 1;
            const int slot = khi * 2 + rhi;
            const int base = (((mb * 8 + kk) * 32 + ga * 4) << 2) + slot;
            #pragma unroll
            for (int j = 0; j < 4; ++j) {
                unsigned int r; CVT_TF32(r, f[j]);
                const float rf = __uint_as_float(r);
                sAr[base + (j << 2)] = rf;
                sAe[base + (j << 2)] = f[j] - rf;
            }
        }
        // ---- stage B = C_pass into fragment layout, split tf32 ----
        #pragma unroll
        for (int it = 0; it < 16; ++it) {
            const int idx = tid + it * 256;    // k*64+u
            const int k = idx >> 6;
            const int u = idx & 63;
            const float val = c00[k * BB + pass] * c01[pass * UU + u]
                            * c10[idx] * c11[idx];
            unsigned int r; CVT_TF32(r, val);
            const float rf = __uint_as_float(r);
            const int kk  = k >> 3;
            const int khi = (k >> 2) & 1;
            const int cc  = k & 3;
            const int nb  = u >> 3;
            const int gg  = u & 7;
            const int base = (((kk * 8 + nb) * 32 + gg * 4 + cc) << 2);
            sB[base + khi]     = rf;
            sB[base + 2 + khi] = val - rf;
        }
        __syncthreads();

        // ---- GEMM: 8 k-steps; term-major MMA order; float4 fragment loads ----
        #pragma unroll
        for (int kk = 0; kk < 8; ++kk) {
            float4 ar4[2], ae4[2], b4[4];
            #pragma unroll
            for (int mt = 0; mt < 2; ++mt) {
                const int mb = mw * 2 + mt;
                const int fi = ((mb * 8 + kk) * 32 + lane) << 2;
                ar4[mt] = *(const float4*)(sAr + fi);
                ae4[mt] = *(const float4*)(sAe + fi);
            }
            #pragma unroll
            for (int nt = 0; nt < 4; ++nt) {
                const int nb = nw * 4 + nt;
                b4[nt] = *(const float4*)(sB + (((kk * 8 + nb) * 32 + lane) << 2));
            }
            // term 0: Xr * Cr
            #pragma unroll
            for (int mt = 0; mt < 2; ++mt)
                #pragma unroll
                for (int nt = 0; nt < 4; ++nt)
                    MMA_TF32(acc[mt][nt],
                             __float_as_uint(ar4[mt].x), __float_as_uint(ar4[mt].y),
                             __float_as_uint(ar4[mt].z), __float_as_uint(ar4[mt].w),
                             __float_as_uint(b4[nt].x),  __float_as_uint(b4[nt].y));
            // term 1: Xe * Cr
            #pragma unroll
            for (int mt = 0; mt < 2; ++mt)
                #pragma unroll
                for (int nt = 0; nt < 4; ++nt)
                    MMA_TF32(acc[mt][nt],
                             __float_as_uint(ae4[mt].x), __float_as_uint(ae4[mt].y),
                             __float_as_uint(ae4[mt].z), __float_as_uint(ae4[mt].w),
                             __float_as_uint(b4[nt].x),  __float_as_uint(b4[nt].y));
            // term 2: Xr * Ce
            #pragma unroll
            for (int mt = 0; mt < 2; ++mt)
                #pragma unroll
                for (int nt = 0; nt < 4; ++nt)
                    MMA_TF32(acc[mt][nt],
                             __float_as_uint(ar4[mt].x), __float_as_uint(ar4[mt].y),
                             __float_as_uint(ar4[mt].z), __float_as_uint(ar4[mt].w),
                             __float_as_uint(b4[nt].z),  __float_as_uint(b4[nt].w));
        }
    }

    // ---- epilogue ----
    const unsigned int* em = mask + (size_t)(n * PP + p) * PP;
    #pragma unroll
    for (int mt = 0; mt < 2; ++mt) {
        #pragma unroll
        for (int nt = 0; nt < 4; ++nt) {
            const int u0e = n0 + 8 * nt + 2 * c;
            const float2 fp2 = *(const float2*)(sFp + u0e);
            const float2 fd2 = *(const float2*)(sFd + u0e);
            #pragma unroll
            for (int half = 0; half < 2; ++half) {
                const int q = m0 + 16 * mt + g + 8 * half;
                const float d0 = acc[mt][nt][2 * half + 0];
                const float d1 = acc[mt][nt][2 * half + 1];
                const float2 fq2 = *(const float2*)(g_Fq + ((size_t)(n * PP + q)) * UU + u0e);
                const float msk = (em[q] != 0u) ? 1.0f : 0.0f;
                const float de = (q == p) ? 1.0f : 0.0f;
                float2 o;
                o.x = (d0 + fq2.x + fp2.x + de * fd2.x) * msk;
                o.y = (d1 + fq2.y + fp2.y + de * fd2.y) * msk;
                *(float2*)(out + (((size_t)(n * PP + p)) * PP + q) * UU + u0e) = o;
            }
        }
    }
}

// ---------------- launch ----------------
extern "C" void kernel_launch(void* const* d_in, const int* in_sizes, int n_in,
                              void* d_out, int out_size) {
    (void)in_sizes; (void)n_in; (void)out_size;
    const float*        x      = (const float*)d_in[0];
    const unsigned int* mask   = (const unsigned int*)d_in[1];
    const float*        npart  = (const float*)d_in[2];
    const float*        alpha0 = (const float*)d_in[3];
    const float*        c00    = (const float*)d_in[4];
    const float*        c01    = (const float*)d_in[5];
    const float*        c10    = (const float*)d_in[6];
    const float*        c11    = (const float*)d_in[7];
    const float*        bias   = (const float*)d_in[8];
    const float*        dbias  = (const float*)d_in[9];
    float* out = (float*)d_out;

    fuse_kernel<<<dim3(NPG, NN), 256>>>(x, npart);
    pro_kernel<<<dim3(32, NN), 256>>>(npart, alpha0, c00, c01, c10, c11, bias, dbias);

    cudaFuncSetAttribute(main_kernel, cudaFuncAttributeMaxDynamicSharedMemorySize,
                         SMEM_FLOATS * 4);
    main_kernel<<<dim3(PP, NN), 256, SMEM_FLOATS * 4>>>(x, mask, c00, c01, c10, c11, out);
}

// round 15
// speedup vs baseline: 1.4055x; 1.4055x over previous
#include <cuda_runtime.h>
#include <cstdint>

#define NN 4
#define PP 128
#define HH 64
#define UU 64
#define BB 15
#define FAVG 49.0f
#define NPG 32   // p-groups for colsum partials (4 p's each)

// ---------------- device scratch ----------------
__device__ float g_rows[NN*HH*PP];
__device__ float g_diag[NN*HH*PP];
__device__ float g_cpart[NPG*NN*PP*HH];
__device__ float g_Fq[NN*PP*UU];
__device__ float g_Fp[NN*PP*UU];
__device__ float g_Fd[NN*PP*UU];

// ---------------- pass 1 (fused): single x read -> rows, diag, colsum partials ----------------
__global__ void __launch_bounds__(256)
fuse_kernel(const float* __restrict__ x, const float* __restrict__ npart) {
    const int pg = blockIdx.x;
    const int n  = blockIdx.y;
    const int p0 = pg * 4;
    const int t  = threadIdx.x;
    const int h4 = t & 15;
    const int qg = t >> 4;

    __shared__ float4 spart[16][4][16];

    const float4* x4 = (const float4*)x;
    const float inv = 1.0f / npart[n];

    float4 col[8];
    #pragma unroll
    for (int j = 0; j < 8; ++j) col[j] = make_float4(0.f, 0.f, 0.f, 0.f);

    #pragma unroll
    for (int p = 0; p < 4; ++p) {
        float4 rp = make_float4(0.f, 0.f, 0.f, 0.f);
        const size_t base = ((size_t)(n * PP + p0 + p)) * PP * 16;
        #pragma unroll
        for (int j = 0; j < 8; ++j) {
            const int q = qg + j * 16;
            const float4 v = x4[base + q * 16 + h4];
            col[j].x += v.x; col[j].y += v.y; col[j].z += v.z; col[j].w += v.w;
            rp.x += v.x; rp.y += v.y; rp.z += v.z; rp.w += v.w;
        }
        spart[qg][p][h4] = rp;
    }
    {
        float4* cp = (float4*)g_cpart + ((size_t)(pg * NN + n)) * PP * 16;
        #pragma unroll
        for (int j = 0; j < 8; ++j)
            cp[(qg + j * 16) * 16 + h4] = col[j];
    }
    __syncthreads();
    if (t < 64) {
        const int p   = t >> 4;
        const int hh4 = t & 15;
        float4 r = spart[0][p][hh4];
        #pragma unroll
        for (int g = 1; g < 16; ++g) {
            const float4 v = spart[g][p][hh4];
            r.x += v.x; r.y += v.y; r.z += v.z; r.w += v.w;
        }
        const int P = p0 + p;
        const int gb = (n * HH + hh4 * 4) * PP + P;
        g_rows[gb + 0*PP] = r.x * inv;
        g_rows[gb + 1*PP] = r.y * inv;
        g_rows[gb + 2*PP] = r.z * inv;
        g_rows[gb + 3*PP] = r.w * inv;
        const float4 d = x4[(((size_t)(n * PP + P)) * PP + P) * 16 + hh4];
        g_diag[gb + 0*PP] = d.x;
        g_diag[gb + 1*PP] = d.y;
        g_diag[gb + 2*PP] = d.z;
        g_diag[gb + 3*PP] = d.w;
    }
}

// ---------------- pass 2 (fused): scalars + coefficients + field GEMMs ----------------
__global__ void __launch_bounds__(256)
pro_kernel(const float* __restrict__ npart,
           const float* __restrict__ alpha0,
           const float* __restrict__ c00,
           const float* __restrict__ c01,
           const float* __restrict__ c10,
           const float* __restrict__ c11,
           const float* __restrict__ bias,
           const float* __restrict__ dbias) {
    const int n  = blockIdx.y;
    const int i0 = blockIdx.x * 4;
    const int tid = threadIdx.x;

    __shared__ float sRR[HH * UU];
    __shared__ float sD[HH][4], sC[HH][4], sR[HH][4];
    __shared__ float sSD[HH], sSA[HH];
    __shared__ float sM[HH][10];
    __shared__ float sA[HH][16];

    const float np  = npart[n];
    const float inv = 1.0f / np;

    #pragma unroll
    for (int it = 0; it < 16; ++it) {
        const int idx = tid + it * 256;
        sRR[idx] = c10[idx] * c11[idx];
    }
    {
        const int hh = tid >> 2;
        const int ii = tid & 3;
        const int gi = (n * HH + hh) * PP + i0 + ii;
        sD[hh][ii] = g_diag[gi];
        sR[hh][ii] = g_rows[gi];
    }
    {
        const int hh = tid & 63;
        const int ii = tid >> 6;
        const float* cp = g_cpart + ((size_t)n * PP + i0 + ii) * HH + hh;
        float s = 0.0f;
        #pragma unroll 8
        for (int g = 0; g < NPG; ++g)
            s += cp[(size_t)g * (NN * PP * HH)];
        sC[hh][ii] = s * inv;
    }
    {
        const int w = tid >> 5, lane = tid & 31;
        #pragma unroll
        for (int j = 0; j < 8; ++j) {
            const int h = w * 8 + j;
            const int base = (n * HH + h) * PP;
            float d = g_diag[base + lane] + g_diag[base + lane + 32]
                    + g_diag[base + lane + 64] + g_diag[base + lane + 96];
            float r = g_rows[base + lane] + g_rows[base + lane + 32]
                    + g_rows[base + lane + 64] + g_rows[base + lane + 96];
            #pragma unroll
            for (int o = 16; o > 0; o >>= 1) {
                d += __shfl_down_sync(0xffffffffu, d, o);
                r += __shfl_down_sync(0xffffffffu, r, o);
            }
            if (lane == 0) { sSD[h] = d * inv; sSA[h] = r * inv; }
        }
    }
    {
        const float ratio = np / FAVG;
        for (int idx = tid; idx < HH * 10; idx += 256)
            sM[idx / 10][idx % 10] = powf(ratio, alpha0[idx]);
    }
    for (int idx = tid; idx < HH * BB; idx += 256)
        sA[idx / BB][idx % BB] = c00[idx];
    __syncthreads();

    const int u  = tid & 63;
    const int ii = tid >> 6;

    float cb[BB];
    #pragma unroll
    for (int b = 2; b < BB; ++b) cb[b] = c01[b * UU + u];

    float aq = 0.0f, ap = 0.0f, ad = 0.0f, vp = 0.0f, vd = 0.0f;

    #pragma unroll 4
    for (int h = 0; h < HH; ++h) {
        const float r = sRR[h * UU + u];
        const float* a = sA[h];
        const float* m = sM[h];
        const float d  = sD[h][ii];
        const float cl = sC[h][ii];
        const float rw = sR[h][ii];
        aq += (a[2]  * cb[2]  * r)        * d
            + (a[5]  * cb[5]  * r * m[0]) * cl
            + (a[6]  * cb[6]  * r * m[1]) * rw;
        ap += (a[3]  * cb[3]  * r)        * d
            + (a[8]  * cb[8]  * r * m[3]) * cl
            + (a[9]  * cb[9]  * r * m[4]) * rw;
        ad += (a[4]  * cb[4]  * r)        * d
            + (a[12] * cb[12] * r * m[7]) * cl
            + (a[11] * cb[11] * r * m[6]) * rw;
        vp += (a[7]  * cb[7]  * r * m[2]) * sSD[h]
            + (a[13] * cb[13] * r * m[8]) * sSA[h];
        vd += (a[10] * cb[10] * r * m[5]) * sSD[h]
            + (a[14] * cb[14] * r * m[9]) * sSA[h];
    }

    const int i = i0 + ii;
    g_Fq[(n * PP + i) * UU + u] = aq + bias[u];
    g_Fp[(n * PP + i) * UU + u] = ap + vp;
    g_Fd[(n * PP + i) * UU + u] = ad + vd + dbias[u];
}

// ---------------- main: tf32 GEMM (2-term compensation: Xr·Cr + Xe·Cr) ----------------
#define SA_STRIDE 68   // [q=128][k=64] pad
#define SB_STRIDE 72   // [k=64][u=64] pad
constexpr int SMEM_FLOATS = 2 * 128 * SA_STRIDE + 64 * SB_STRIDE + 128;  // ~89KB

#define CVT_TF32(r, f) asm("cvt.rna.tf32.f32 %0, %1;" : "=r"(r) : "f"(f))
#define MMA_TF32(d, a, b0_, b1_) \
    asm volatile("mma.sync.aligned.m16n8k8.row.col.f32.tf32.tf32.f32 " \
        "{%0,%1,%2,%3},{%4,%5,%6,%7},{%8,%9},{%0,%1,%2,%3};" \
        : "+f"(d[0]), "+f"(d[1]), "+f"(d[2]), "+f"(d[3]) \
        : "r"(a[0]), "r"(a[1]), "r"(a[2]), "r"(a[3]), "r"(b0_), "r"(b1_))

__global__ void __launch_bounds__(256, 2)
main_kernel(const float* __restrict__ x,
            const unsigned int* __restrict__ mask,
            const float* __restrict__ c00,
            const float* __restrict__ c01,
            const float* __restrict__ c10,
            const float* __restrict__ c11,
            float* __restrict__ out) {
    extern __shared__ float sm[];
    float* sXr = sm;                          // [128][68]
    float* sXe = sXr + 128 * SA_STRIDE;       // [128][68]
    float* sBr = sXe + 128 * SA_STRIDE;       // [64][72]
    float* sFp = sBr + 64 * SB_STRIDE;        // [64]
    float* sFd = sFp + 64;                    // [64]

    const int p = blockIdx.x;
    const int n = blockIdx.y;
    const int tid = threadIdx.x;
    const int lane = tid & 31;
    const int w = tid >> 5;
    const int mw = w & 3;                     // 4 m-warps
    const int nw = w >> 2;                    // 2 n-warps
    const int g = lane >> 2;
    const int c = lane & 3;
    const int m0 = mw * 32;
    const int n0 = nw * 32;

    if (tid < 64) {
        sFp[tid] = g_Fp[(n * PP + p) * UU + tid];
        sFd[tid] = g_Fd[(n * PP + p) * UU + tid];
    }

    float acc[2][4][4];
    #pragma unroll
    for (int mt = 0; mt < 2; ++mt)
        #pragma unroll
        for (int nt = 0; nt < 4; ++nt)
            #pragma unroll
            for (int j = 0; j < 4; ++j) acc[mt][nt][j] = 0.0f;

    #pragma unroll 1
    for (int pass = 0; pass < 2; ++pass) {
        if (pass > 0) __syncthreads();

        // ---- fill X (direct for pass 0, transposed for pass 1), split tf32 ----
        if (pass == 0) {
            const float4* xrow4 = (const float4*)(x + ((size_t)(n * PP + p)) * PP * HH);
            #pragma unroll
            for (int it = 0; it < 8; ++it) {
                const int idx4 = tid + it * 256;
                const float4 v = xrow4[idx4];
                const int q  = idx4 >> 4;
                const int h0 = (idx4 & 15) << 2;
                const float f[4] = {v.x, v.y, v.z, v.w};
                #pragma unroll
                for (int j = 0; j < 4; ++j) {
                    unsigned int r; CVT_TF32(r, f[j]);
                    const float rf = __uint_as_float(r);
                    sXr[q * SA_STRIDE + h0 + j] = rf;
                    sXe[q * SA_STRIDE + h0 + j] = f[j] - rf;
                }
            }
        } else {
            const int h0 = (tid & 15) << 2;
            #pragma unroll
            for (int it = 0; it < 8; ++it) {
                const int r = (tid >> 4) + it * 16;
                const float4 v = *(const float4*)(x + (((size_t)(n * PP + r)) * PP + p) * HH + h0);
                const float f[4] = {v.x, v.y, v.z, v.w};
                #pragma unroll
                for (int j = 0; j < 4; ++j) {
                    unsigned int rr; CVT_TF32(rr, f[j]);
                    const float rf = __uint_as_float(rr);
                    sXr[r * SA_STRIDE + h0 + j] = rf;
                    sXe[r * SA_STRIDE + h0 + j] = f[j] - rf;
                }
            }
        }
        // ---- fill B = C_pass (k x u), tf32-rounded only (Ce term dropped) ----
        {
            const int bsel = pass;
            #pragma unroll
            for (int it = 0; it < 16; ++it) {
                const int idx = tid + it * 256;    // k*64+u
                const int k = idx >> 6;
                const int u = idx & 63;
                const float val = c00[k * BB + bsel] * c01[bsel * UU + u]
                                * c10[idx] * c11[idx];
                unsigned int r; CVT_TF32(r, val);
                sBr[k * SB_STRIDE + u] = __uint_as_float(r);
            }
        }
        __syncthreads();

        // ---- tensor-core GEMM: 8 k-steps, term-major (RAW distance 8) ----
        #pragma unroll
        for (int kk = 0; kk < 8; ++kk) {
            const int ka = kk * 8 + c;
            unsigned int ar[2][4], ae[2][4];
            #pragma unroll
            for (int mt = 0; mt < 2; ++mt) {
                const int row = m0 + 16 * mt + g;
                ar[mt][0] = __float_as_uint(sXr[row * SA_STRIDE + ka]);
                ar[mt][1] = __float_as_uint(sXr[(row + 8) * SA_STRIDE + ka]);
                ar[mt][2] = __float_as_uint(sXr[row * SA_STRIDE + ka + 4]);
                ar[mt][3] = __float_as_uint(sXr[(row + 8) * SA_STRIDE + ka + 4]);
                ae[mt][0] = __float_as_uint(sXe[row * SA_STRIDE + ka]);
                ae[mt][1] = __float_as_uint(sXe[(row + 8) * SA_STRIDE + ka]);
                ae[mt][2] = __float_as_uint(sXe[row * SA_STRIDE + ka + 4]);
                ae[mt][3] = __float_as_uint(sXe[(row + 8) * SA_STRIDE + ka + 4]);
            }
            unsigned int br0[4], br1[4];
            #pragma unroll
            for (int nt = 0; nt < 4; ++nt) {
                const int col = n0 + 8 * nt + g;
                br0[nt] = __float_as_uint(sBr[(kk * 8 + c) * SB_STRIDE + col]);
                br1[nt] = __float_as_uint(sBr[(kk * 8 + 4 + c) * SB_STRIDE + col]);
            }
            // term 0: Xr * Cr (8 independent MMAs)
            #pragma unroll
            for (int mt = 0; mt < 2; ++mt)
                #pragma unroll
                for (int nt = 0; nt < 4; ++nt)
                    MMA_TF32(acc[mt][nt], ar[mt], br0[nt], br1[nt]);
            // term 1: Xe * Cr (8 independent MMAs)
            #pragma unroll
            for (int mt = 0; mt < 2; ++mt)
                #pragma unroll
                for (int nt = 0; nt < 4; ++nt)
                    MMA_TF32(acc[mt][nt], ae[mt], br0[nt], br1[nt]);
        }
    }

    // ---- epilogue ----
    const unsigned int* em = mask + (size_t)(n * PP + p) * PP;
    #pragma unroll
    for (int mt = 0; mt < 2; ++mt) {
        #pragma unroll
        for (int nt = 0; nt < 4; ++nt) {
            const int u0e = n0 + 8 * nt + 2 * c;
            const float2 fp2 = *(const float2*)(sFp + u0e);
            const float2 fd2 = *(const float2*)(sFd + u0e);
            #pragma unroll
            for (int half = 0; half < 2; ++half) {
                const int q = m0 + 16 * mt + g + 8 * half;
                const float d0 = acc[mt][nt][2 * half + 0];
                const float d1 = acc[mt][nt][2 * half + 1];
                const float2 fq2 = *(const float2*)(g_Fq + ((size_t)(n * PP + q)) * UU + u0e);
                const float msk = (em[q] != 0u) ? 1.0f : 0.0f;
                const float de = (q == p) ? 1.0f : 0.0f;
                float2 o;
                o.x = (d0 + fq2.x + fp2.x + de * fd2.x) * msk;
                o.y = (d1 + fq2.y + fp2.y + de * fd2.y) * msk;
                *(float2*)(out + (((size_t)(n * PP + p)) * PP + q) * UU + u0e) = o;
            }
        }
    }
}

// ---------------- launch ----------------
extern "C" void kernel_launch(void* const* d_in, const int* in_sizes, int n_in,
                              void* d_out, int out_size) {
    (void)in_sizes; (void)n_in; (void)out_size;
    const float*        x      = (const float*)d_in[0];
    const unsigned int* mask   = (const unsigned int*)d_in[1];
    const float*        npart  = (const float*)d_in[2];
    const float*        alpha0 = (const float*)d_in[3];
    const float*        c00    = (const float*)d_in[4];
    const float*        c01    = (const float*)d_in[5];
    const float*        c10    = (const float*)d_in[6];
    const float*        c11    = (const float*)d_in[7];
    const float*        bias   = (const float*)d_in[8];
    const float*        dbias  = (const float*)d_in[9];
    float* out = (float*)d_out;

    fuse_kernel<<<dim3(NPG, NN), 256>>>(x, npart);
    pro_kernel<<<dim3(32, NN), 256>>>(npart, alpha0, c00, c01, c10, c11, bias, dbias);

    cudaFuncSetAttribute(main_kernel, cudaFuncAttributeMaxDynamicSharedMemorySize,
                         SMEM_FLOATS * 4);
    main_kernel<<<dim3(PP, NN), 256, SMEM_FLOATS * 4>>>(x, mask, c00, c01, c10, c11, out);
}

// round 16
// speedup vs baseline: 1.4914x; 1.0611x over previous
#include <cuda_runtime.h>
#include <cstdint>

#define NN 4
#define PP 128
#define HH 64
#define UU 64
#define BB 15
#define FAVG 49.0f
#define NPG 32   // p-groups for colsum partials (4 p's each)

// ---------------- device scratch ----------------
__device__ float g_rows[NN*HH*PP];
__device__ float g_diag[NN*HH*PP];
__device__ float g_cpart[NPG*NN*PP*HH];
__device__ float g_Fq[NN*PP*UU];
__device__ float g_Fp[NN*PP*UU];
__device__ float g_Fd[NN*PP*UU];

// ---------------- pass 1 (fused): single x read -> rows, diag, colsum partials ----------------
__global__ void __launch_bounds__(256)
fuse_kernel(const float* __restrict__ x, const float* __restrict__ npart) {
    const int pg = blockIdx.x;
    const int n  = blockIdx.y;
    const int p0 = pg * 4;
    const int t  = threadIdx.x;
    const int h4 = t & 15;
    const int qg = t >> 4;

    __shared__ float4 spart[16][4][16];

    const float4* x4 = (const float4*)x;
    const float inv = 1.0f / npart[n];

    float4 col[8];
    #pragma unroll
    for (int j = 0; j < 8; ++j) col[j] = make_float4(0.f, 0.f, 0.f, 0.f);

    #pragma unroll
    for (int p = 0; p < 4; ++p) {
        float4 rp = make_float4(0.f, 0.f, 0.f, 0.f);
        const size_t base = ((size_t)(n * PP + p0 + p)) * PP * 16;
        #pragma unroll
        for (int j = 0; j < 8; ++j) {
            const int q = qg + j * 16;
            const float4 v = x4[base + q * 16 + h4];
            col[j].x += v.x; col[j].y += v.y; col[j].z += v.z; col[j].w += v.w;
            rp.x += v.x; rp.y += v.y; rp.z += v.z; rp.w += v.w;
        }
        spart[qg][p][h4] = rp;
    }
    {
        float4* cp = (float4*)g_cpart + ((size_t)(pg * NN + n)) * PP * 16;
        #pragma unroll
        for (int j = 0; j < 8; ++j)
            cp[(qg + j * 16) * 16 + h4] = col[j];
    }
    __syncthreads();
    if (t < 64) {
        const int p   = t >> 4;
        const int hh4 = t & 15;
        float4 r = spart[0][p][hh4];
        #pragma unroll
        for (int g = 1; g < 16; ++g) {
            const float4 v = spart[g][p][hh4];
            r.x += v.x; r.y += v.y; r.z += v.z; r.w += v.w;
        }
        const int P = p0 + p;
        const int gb = (n * HH + hh4 * 4) * PP + P;
        g_rows[gb + 0*PP] = r.x * inv;
        g_rows[gb + 1*PP] = r.y * inv;
        g_rows[gb + 2*PP] = r.z * inv;
        g_rows[gb + 3*PP] = r.w * inv;
        const float4 d = x4[(((size_t)(n * PP + P)) * PP + P) * 16 + hh4];
        g_diag[gb + 0*PP] = d.x;
        g_diag[gb + 1*PP] = d.y;
        g_diag[gb + 2*PP] = d.z;
        g_diag[gb + 3*PP] = d.w;
    }
}

// ---------------- pass 2 (fused): scalars + coefficients + field GEMMs ----------------
__global__ void __launch_bounds__(256)
pro_kernel(const float* __restrict__ npart,
           const float* __restrict__ alpha0,
           const float* __restrict__ c00,
           const float* __restrict__ c01,
           const float* __restrict__ c10,
           const float* __restrict__ c11,
           const float* __restrict__ bias,
           const float* __restrict__ dbias) {
    const int n  = blockIdx.y;
    const int i0 = blockIdx.x * 4;
    const int tid = threadIdx.x;

    __shared__ float sRR[HH * UU];
    __shared__ float sD[HH][4], sC[HH][4], sR[HH][4];
    __shared__ float sSD[HH], sSA[HH];
    __shared__ float sM[HH][10];
    __shared__ float sA[HH][16];

    const float np  = npart[n];
    const float inv = 1.0f / np;

    #pragma unroll
    for (int it = 0; it < 16; ++it) {
        const int idx = tid + it * 256;
        sRR[idx] = c10[idx] * c11[idx];
    }
    {
        const int hh = tid >> 2;
        const int ii = tid & 3;
        const int gi = (n * HH + hh) * PP + i0 + ii;
        sD[hh][ii] = g_diag[gi];
        sR[hh][ii] = g_rows[gi];
    }
    {
        const int hh = tid & 63;
        const int ii = tid >> 6;
        const float* cp = g_cpart + ((size_t)n * PP + i0 + ii) * HH + hh;
        float s = 0.0f;
        #pragma unroll 8
        for (int g = 0; g < NPG; ++g)
            s += cp[(size_t)g * (NN * PP * HH)];
        sC[hh][ii] = s * inv;
    }
    {
        const int w = tid >> 5, lane = tid & 31;
        #pragma unroll
        for (int j = 0; j < 8; ++j) {
            const int h = w * 8 + j;
            const int base = (n * HH + h) * PP;
            float d = g_diag[base + lane] + g_diag[base + lane + 32]
                    + g_diag[base + lane + 64] + g_diag[base + lane + 96];
            float r = g_rows[base + lane] + g_rows[base + lane + 32]
                    + g_rows[base + lane + 64] + g_rows[base + lane + 96];
            #pragma unroll
            for (int o = 16; o > 0; o >>= 1) {
                d += __shfl_down_sync(0xffffffffu, d, o);
                r += __shfl_down_sync(0xffffffffu, r, o);
            }
            if (lane == 0) { sSD[h] = d * inv; sSA[h] = r * inv; }
        }
    }
    {
        const float ratio = np / FAVG;
        for (int idx = tid; idx < HH * 10; idx += 256)
            sM[idx / 10][idx % 10] = powf(ratio, alpha0[idx]);
    }
    for (int idx = tid; idx < HH * BB; idx += 256)
        sA[idx / BB][idx % BB] = c00[idx];
    __syncthreads();

    const int u  = tid & 63;
    const int ii = tid >> 6;

    float cb[BB];
    #pragma unroll
    for (int b = 2; b < BB; ++b) cb[b] = c01[b * UU + u];

    float aq = 0.0f, ap = 0.0f, ad = 0.0f, vp = 0.0f, vd = 0.0f;

    #pragma unroll 4
    for (int h = 0; h < HH; ++h) {
        const float r = sRR[h * UU + u];
        const float* a = sA[h];
        const float* m = sM[h];
        const float d  = sD[h][ii];
        const float cl = sC[h][ii];
        const float rw = sR[h][ii];
        aq += (a[2]  * cb[2]  * r)        * d
            + (a[5]  * cb[5]  * r * m[0]) * cl
            + (a[6]  * cb[6]  * r * m[1]) * rw;
        ap += (a[3]  * cb[3]  * r)        * d
            + (a[8]  * cb[8]  * r * m[3]) * cl
            + (a[9]  * cb[9]  * r * m[4]) * rw;
        ad += (a[4]  * cb[4]  * r)        * d
            + (a[12] * cb[12] * r * m[7]) * cl
            + (a[11] * cb[11] * r * m[6]) * rw;
        vp += (a[7]  * cb[7]  * r * m[2]) * sSD[h]
            + (a[13] * cb[13] * r * m[8]) * sSA[h];
        vd += (a[10] * cb[10] * r * m[5]) * sSD[h]
            + (a[14] * cb[14] * r * m[9]) * sSA[h];
    }

    const int i = i0 + ii;
    g_Fq[(n * PP + i) * UU + u] = aq + bias[u];
    g_Fp[(n * PP + i) * UU + u] = ap + vp;
    g_Fd[(n * PP + i) * UU + u] = ad + vd + dbias[u];
}

// ---------------- main: pure tf32 GEMM (single term; X and C both rna-tf32) ----------------
#define SA_STRIDE 68   // [q=128][k=64] pad
#define SB_STRIDE 72   // [k=64][u=64] pad
constexpr int SMEM_FLOATS = 128 * SA_STRIDE + 64 * SB_STRIDE + 128;  // 13440 = 52.5KB

#define CVT_TF32(r, f) asm("cvt.rna.tf32.f32 %0, %1;" : "=r"(r) : "f"(f))
#define MMA_TF32(d, a, b0_, b1_) \
    asm volatile("mma.sync.aligned.m16n8k8.row.col.f32.tf32.tf32.f32 " \
        "{%0,%1,%2,%3},{%4,%5,%6,%7},{%8,%9},{%0,%1,%2,%3};" \
        : "+f"(d[0]), "+f"(d[1]), "+f"(d[2]), "+f"(d[3]) \
        : "r"(a[0]), "r"(a[1]), "r"(a[2]), "r"(a[3]), "r"(b0_), "r"(b1_))

__global__ void __launch_bounds__(256, 3)
main_kernel(const float* __restrict__ x,
            const unsigned int* __restrict__ mask,
            const float* __restrict__ c00,
            const float* __restrict__ c01,
            const float* __restrict__ c10,
            const float* __restrict__ c11,
            float* __restrict__ out) {
    extern __shared__ float sm[];
    float* sXr = sm;                          // [128][68]
    float* sBr = sXr + 128 * SA_STRIDE;       // [64][72]
    float* sFp = sBr + 64 * SB_STRIDE;        // [64]
    float* sFd = sFp + 64;                    // [64]

    const int p = blockIdx.x;
    const int n = blockIdx.y;
    const int tid = threadIdx.x;
    const int lane = tid & 31;
    const int w = tid >> 5;
    const int mw = w & 3;                     // 4 m-warps
    const int nw = w >> 2;                    // 2 n-warps
    const int g = lane >> 2;
    const int c = lane & 3;
    const int m0 = mw * 32;
    const int n0 = nw * 32;

    if (tid < 64) {
        sFp[tid] = g_Fp[(n * PP + p) * UU + tid];
        sFd[tid] = g_Fd[(n * PP + p) * UU + tid];
    }

    float acc[2][4][4];
    #pragma unroll
    for (int mt = 0; mt < 2; ++mt)
        #pragma unroll
        for (int nt = 0; nt < 4; ++nt)
            #pragma unroll
            for (int j = 0; j < 4; ++j) acc[mt][nt][j] = 0.0f;

    #pragma unroll 1
    for (int pass = 0; pass < 2; ++pass) {
        if (pass > 0) __syncthreads();

        // ---- fill X (direct for pass 0, transposed for pass 1), rna-tf32 ----
        if (pass == 0) {
            const float4* xrow4 = (const float4*)(x + ((size_t)(n * PP + p)) * PP * HH);
            #pragma unroll
            for (int it = 0; it < 8; ++it) {
                const int idx4 = tid + it * 256;
                const float4 v = xrow4[idx4];
                const int q  = idx4 >> 4;
                const int h0 = (idx4 & 15) << 2;
                const float f[4] = {v.x, v.y, v.z, v.w};
                #pragma unroll
                for (int j = 0; j < 4; ++j) {
                    unsigned int r; CVT_TF32(r, f[j]);
                    sXr[q * SA_STRIDE + h0 + j] = __uint_as_float(r);
                }
            }
        } else {
            const int h0 = (tid & 15) << 2;
            #pragma unroll
            for (int it = 0; it < 8; ++it) {
                const int r = (tid >> 4) + it * 16;
                const float4 v = *(const float4*)(x + (((size_t)(n * PP + r)) * PP + p) * HH + h0);
                const float f[4] = {v.x, v.y, v.z, v.w};
                #pragma unroll
                for (int j = 0; j < 4; ++j) {
                    unsigned int rr; CVT_TF32(rr, f[j]);
                    sXr[r * SA_STRIDE + h0 + j] = __uint_as_float(rr);
                }
            }
        }
        // ---- fill B = C_pass (k x u), rna-tf32 ----
        {
            const int bsel = pass;
            #pragma unroll
            for (int it = 0; it < 16; ++it) {
                const int idx = tid + it * 256;    // k*64+u
                const int k = idx >> 6;
                const int u = idx & 63;
                const float val = c00[k * BB + bsel] * c01[bsel * UU + u]
                                * c10[idx] * c11[idx];
                unsigned int r; CVT_TF32(r, val);
                sBr[k * SB_STRIDE + u] = __uint_as_float(r);
            }
        }
        __syncthreads();

        // ---- tensor-core GEMM: 8 k-steps, 8 independent MMAs each ----
        #pragma unroll
        for (int kk = 0; kk < 8; ++kk) {
            const int ka = kk * 8 + c;
            unsigned int ar[2][4];
            #pragma unroll
            for (int mt = 0; mt < 2; ++mt) {
                const int row = m0 + 16 * mt + g;
                ar[mt][0] = __float_as_uint(sXr[row * SA_STRIDE + ka]);
                ar[mt][1] = __float_as_uint(sXr[(row + 8) * SA_STRIDE + ka]);
                ar[mt][2] = __float_as_uint(sXr[row * SA_STRIDE + ka + 4]);
                ar[mt][3] = __float_as_uint(sXr[(row + 8) * SA_STRIDE + ka + 4]);
            }
            unsigned int br0[4], br1[4];
            #pragma unroll
            for (int nt = 0; nt < 4; ++nt) {
                const int col = n0 + 8 * nt + g;
                br0[nt] = __float_as_uint(sBr[(kk * 8 + c) * SB_STRIDE + col]);
                br1[nt] = __float_as_uint(sBr[(kk * 8 + 4 + c) * SB_STRIDE + col]);
            }
            #pragma unroll
            for (int mt = 0; mt < 2; ++mt)
                #pragma unroll
                for (int nt = 0; nt < 4; ++nt)
                    MMA_TF32(acc[mt][nt], ar[mt], br0[nt], br1[nt]);
        }
    }

    // ---- epilogue ----
    const unsigned int* em = mask + (size_t)(n * PP + p) * PP;
    #pragma unroll
    for (int mt = 0; mt < 2; ++mt) {
        #pragma unroll
        for (int nt = 0; nt < 4; ++nt) {
            const int u0e = n0 + 8 * nt + 2 * c;
            const float2 fp2 = *(const float2*)(sFp + u0e);
            const float2 fd2 = *(const float2*)(sFd + u0e);
            #pragma unroll
            for (int half = 0; half < 2; ++half) {
                const int q = m0 + 16 * mt + g + 8 * half;
                const float d0 = acc[mt][nt][2 * half + 0];
                const float d1 = acc[mt][nt][2 * half + 1];
                const float2 fq2 = *(const float2*)(g_Fq + ((size_t)(n * PP + q)) * UU + u0e);
                const float msk = (em[q] != 0u) ? 1.0f : 0.0f;
                const float de = (q == p) ? 1.0f : 0.0f;
                float2 o;
                o.x = (d0 + fq2.x + fp2.x + de * fd2.x) * msk;
                o.y = (d1 + fq2.y + fp2.y + de * fd2.y) * msk;
                *(float2*)(out + (((size_t)(n * PP + p)) * PP + q) * UU + u0e) = o;
            }
        }
    }
}

// ---------------- launch ----------------
extern "C" void kernel_launch(void* const* d_in, const int* in_sizes, int n_in,
                              void* d_out, int out_size) {
    (void)in_sizes; (void)n_in; (void)out_size;
    const float*        x      = (const float*)d_in[0];
    const unsigned int* mask   = (const unsigned int*)d_in[1];
    const float*        npart  = (const float*)d_in[2];
    const float*        alpha0 = (const float*)d_in[3];
    const float*        c00    = (const float*)d_in[4];
    const float*        c01    = (const float*)d_in[5];
    const float*        c10    = (const float*)d_in[6];
    const float*        c11    = (const float*)d_in[7];
    const float*        bias   = (const float*)d_in[8];
    const float*        dbias  = (const float*)d_in[9];
    float* out = (float*)d_out;

    fuse_kernel<<<dim3(NPG, NN), 256>>>(x, npart);
    pro_kernel<<<dim3(32, NN), 256>>>(npart, alpha0, c00, c01, c10, c11, bias, dbias);

    cudaFuncSetAttribute(main_kernel, cudaFuncAttributeMaxDynamicSharedMemorySize,
                         SMEM_FLOATS * 4);
    main_kernel<<<dim3(PP, NN), 256, SMEM_FLOATS * 4>>>(x, mask, c00, c01, c10, c11, out);
}

// round 17
// speedup vs baseline: 1.6129x; 1.0815x over previous
#include <cuda_runtime.h>
#include <cstdint>

#define NN 4
#define PP 128
#define HH 64
#define UU 64
#define BB 15
#define FAVG 49.0f
#define NPG 32   // p-groups for colsum partials (4 p's each)
#define SB_STRIDE 72

// ---------------- device scratch ----------------
__device__ float g_rows[NN*HH*PP];
__device__ float g_diag[NN*HH*PP];
__device__ float g_cpart[NPG*NN*PP*HH];
__device__ float g_Fq[NN*PP*UU];
__device__ float g_Fp[NN*PP*UU];
__device__ float g_Fd[NN*PP*UU];
__device__ float g_B[2*HH*SB_STRIDE];      // tf32-rounded C0/C1, padded [pass][k][u]

#define CVT_TF32(r, f) asm("cvt.rna.tf32.f32 %0, %1;" : "=r"(r) : "f"(f))

// ---------------- pass 1 (fused): single x read -> rows, diag, colsum partials ----------------
__global__ void __launch_bounds__(256)
fuse_kernel(const float* __restrict__ x, const float* __restrict__ npart) {
    const int pg = blockIdx.x;
    const int n  = blockIdx.y;
    const int p0 = pg * 4;
    const int t  = threadIdx.x;
    const int h4 = t & 15;
    const int qg = t >> 4;

    __shared__ float4 spart[16][4][16];

    const float4* x4 = (const float4*)x;
    const float inv = 1.0f / npart[n];

    float4 col[8];
    #pragma unroll
    for (int j = 0; j < 8; ++j) col[j] = make_float4(0.f, 0.f, 0.f, 0.f);

    #pragma unroll
    for (int p = 0; p < 4; ++p) {
        float4 rp = make_float4(0.f, 0.f, 0.f, 0.f);
        const size_t base = ((size_t)(n * PP + p0 + p)) * PP * 16;
        #pragma unroll
        for (int j = 0; j < 8; ++j) {
            const int q = qg + j * 16;
            const float4 v = x4[base + q * 16 + h4];
            col[j].x += v.x; col[j].y += v.y; col[j].z += v.z; col[j].w += v.w;
            rp.x += v.x; rp.y += v.y; rp.z += v.z; rp.w += v.w;
        }
        spart[qg][p][h4] = rp;
    }
    {
        float4* cp = (float4*)g_cpart + ((size_t)(pg * NN + n)) * PP * 16;
        #pragma unroll
        for (int j = 0; j < 8; ++j)
            cp[(qg + j * 16) * 16 + h4] = col[j];
    }
    __syncthreads();
    if (t < 64) {
        const int p   = t >> 4;
        const int hh4 = t & 15;
        float4 r = spart[0][p][hh4];
        #pragma unroll
        for (int g = 1; g < 16; ++g) {
            const float4 v = spart[g][p][hh4];
            r.x += v.x; r.y += v.y; r.z += v.z; r.w += v.w;
        }
        const int P = p0 + p;
        const int gb = (n * HH + hh4 * 4) * PP + P;
        g_rows[gb + 0*PP] = r.x * inv;
        g_rows[gb + 1*PP] = r.y * inv;
        g_rows[gb + 2*PP] = r.z * inv;
        g_rows[gb + 3*PP] = r.w * inv;
        const float4 d = x4[(((size_t)(n * PP + P)) * PP + P) * 16 + hh4];
        g_diag[gb + 0*PP] = d.x;
        g_diag[gb + 1*PP] = d.y;
        g_diag[gb + 2*PP] = d.z;
        g_diag[gb + 3*PP] = d.w;
    }
}

// ---------------- pass 2 (fused): scalars + coefficients + field GEMMs + B build ----------------
__global__ void __launch_bounds__(256)
pro_kernel(const float* __restrict__ npart,
           const float* __restrict__ alpha0,
           const float* __restrict__ c00,
           const float* __restrict__ c01,
           const float* __restrict__ c10,
           const float* __restrict__ c11,
           const float* __restrict__ bias,
           const float* __restrict__ dbias) {
    const int n  = blockIdx.y;
    const int i0 = blockIdx.x * 4;
    const int tid = threadIdx.x;

    __shared__ float sRR[HH * UU];
    __shared__ float sD[HH][4], sC[HH][4], sR[HH][4];
    __shared__ float sSD[HH], sSA[HH];
    __shared__ float sM[HH][10];
    __shared__ float sA[HH][16];

    const float np  = npart[n];
    const float inv = 1.0f / np;

    #pragma unroll
    for (int it = 0; it < 16; ++it) {
        const int idx = tid + it * 256;
        sRR[idx] = c10[idx] * c11[idx];
    }
    // build tf32 B matrices once (block (0, n=0) only; all blocks compute sRR anyway)
    if (blockIdx.x == 0 && n == 0) {
        #pragma unroll
        for (int it = 0; it < 16; ++it) {
            const int idx = tid + it * 256;    // k*64+u
            const int k = idx >> 6;
            const int u = idx & 63;
            const float rr = c10[idx] * c11[idx];
            const float v0 = c00[k * BB + 0] * c01[0 * UU + u] * rr;
            const float v1 = c00[k * BB + 1] * c01[1 * UU + u] * rr;
            unsigned int r0, r1;
            CVT_TF32(r0, v0);
            CVT_TF32(r1, v1);
            g_B[k * SB_STRIDE + u]                    = __uint_as_float(r0);
            g_B[HH * SB_STRIDE + k * SB_STRIDE + u]   = __uint_as_float(r1);
        }
    }
    {
        const int hh = tid >> 2;
        const int ii = tid & 3;
        const int gi = (n * HH + hh) * PP + i0 + ii;
        sD[hh][ii] = g_diag[gi];
        sR[hh][ii] = g_rows[gi];
    }
    {
        const int hh = tid & 63;
        const int ii = tid >> 6;
        const float* cp = g_cpart + ((size_t)n * PP + i0 + ii) * HH + hh;
        float s = 0.0f;
        #pragma unroll 8
        for (int g = 0; g < NPG; ++g)
            s += cp[(size_t)g * (NN * PP * HH)];
        sC[hh][ii] = s * inv;
    }
    {
        const int w = tid >> 5, lane = tid & 31;
        #pragma unroll
        for (int j = 0; j < 8; ++j) {
            const int h = w * 8 + j;
            const int base = (n * HH + h) * PP;
            float d = g_diag[base + lane] + g_diag[base + lane + 32]
                    + g_diag[base + lane + 64] + g_diag[base + lane + 96];
            float r = g_rows[base + lane] + g_rows[base + lane + 32]
                    + g_rows[base + lane + 64] + g_rows[base + lane + 96];
            #pragma unroll
            for (int o = 16; o > 0; o >>= 1) {
                d += __shfl_down_sync(0xffffffffu, d, o);
                r += __shfl_down_sync(0xffffffffu, r, o);
            }
            if (lane == 0) { sSD[h] = d * inv; sSA[h] = r * inv; }
        }
    }
    {
        const float ratio = np / FAVG;
        for (int idx = tid; idx < HH * 10; idx += 256)
            sM[idx / 10][idx % 10] = powf(ratio, alpha0[idx]);
    }
    for (int idx = tid; idx < HH * BB; idx += 256)
        sA[idx / BB][idx % BB] = c00[idx];
    __syncthreads();

    const int u  = tid & 63;
    const int ii = tid >> 6;

    float cb[BB];
    #pragma unroll
    for (int b = 2; b < BB; ++b) cb[b] = c01[b * UU + u];

    float aq = 0.0f, ap = 0.0f, ad = 0.0f, vp = 0.0f, vd = 0.0f;

    #pragma unroll 4
    for (int h = 0; h < HH; ++h) {
        const float r = sRR[h * UU + u];
        const float* a = sA[h];
        const float* m = sM[h];
        const float d  = sD[h][ii];
        const float cl = sC[h][ii];
        const float rw = sR[h][ii];
        aq += (a[2]  * cb[2]  * r)        * d
            + (a[5]  * cb[5]  * r * m[0]) * cl
            + (a[6]  * cb[6]  * r * m[1]) * rw;
        ap += (a[3]  * cb[3]  * r)        * d
            + (a[8]  * cb[8]  * r * m[3]) * cl
            + (a[9]  * cb[9]  * r * m[4]) * rw;
        ad += (a[4]  * cb[4]  * r)        * d
            + (a[12] * cb[12] * r * m[7]) * cl
            + (a[11] * cb[11] * r * m[6]) * rw;
        vp += (a[7]  * cb[7]  * r * m[2]) * sSD[h]
            + (a[13] * cb[13] * r * m[8]) * sSA[h];
        vd += (a[10] * cb[10] * r * m[5]) * sSD[h]
            + (a[14] * cb[14] * r * m[9]) * sSA[h];
    }

    const int i = i0 + ii;
    g_Fq[(n * PP + i) * UU + u] = aq + bias[u];
    g_Fp[(n * PP + i) * UU + u] = ap + vp;
    g_Fd[(n * PP + i) * UU + u] = ad + vd + dbias[u];
}

// ---------------- main: pure tf32 GEMM, B pre-built, both B buffers resident ----------------
#define SA_STRIDE 68
constexpr int SMEM_FLOATS = 128 * SA_STRIDE + 2 * 64 * SB_STRIDE + 128;  // 17664 = 69KB

#define MMA_TF32(d, a, b0_, b1_) \
    asm volatile("mma.sync.aligned.m16n8k8.row.col.f32.tf32.tf32.f32 " \
        "{%0,%1,%2,%3},{%4,%5,%6,%7},{%8,%9},{%0,%1,%2,%3};" \
        : "+f"(d[0]), "+f"(d[1]), "+f"(d[2]), "+f"(d[3]) \
        : "r"(a[0]), "r"(a[1]), "r"(a[2]), "r"(a[3]), "r"(b0_), "r"(b1_))

__global__ void __launch_bounds__(256, 3)
main_kernel(const float* __restrict__ x,
            const unsigned int* __restrict__ mask,
            float* __restrict__ out) {
    extern __shared__ float sm[];
    float* sXr = sm;                          // [128][68]
    float* sB  = sXr + 128 * SA_STRIDE;       // [2][64][72]
    float* sFp = sB + 2 * 64 * SB_STRIDE;     // [64]
    float* sFd = sFp + 64;                    // [64]

    const int p = blockIdx.x;
    const int n = blockIdx.y;
    const int tid = threadIdx.x;
    const int lane = tid & 31;
    const int w = tid >> 5;
    const int mw = w & 3;
    const int nw = w >> 2;
    const int g = lane >> 2;
    const int c = lane & 3;
    const int m0 = mw * 32;
    const int n0 = nw * 32;

    // stage both B buffers once (float4, L2-resident source)
    {
        const float4* src = (const float4*)g_B;
        float4* dst = (float4*)sB;
        #pragma unroll
        for (int it = 0; it < 9; ++it) {
            const int i4 = tid + it * 256;    // 2*64*72/4 = 2304
            if (i4 < 2304) dst[i4] = src[i4];
        }
    }
    if (tid < 64) {
        sFp[tid] = g_Fp[(n * PP + p) * UU + tid];
        sFd[tid] = g_Fd[(n * PP + p) * UU + tid];
    }

    float acc[2][4][4];
    #pragma unroll
    for (int mt = 0; mt < 2; ++mt)
        #pragma unroll
        for (int nt = 0; nt < 4; ++nt)
            #pragma unroll
            for (int j = 0; j < 4; ++j) acc[mt][nt][j] = 0.0f;

    #pragma unroll 1
    for (int pass = 0; pass < 2; ++pass) {
        if (pass > 0) __syncthreads();

        // ---- fill X (direct / transposed), rna-tf32 ----
        if (pass == 0) {
            const float4* xrow4 = (const float4*)(x + ((size_t)(n * PP + p)) * PP * HH);
            #pragma unroll
            for (int it = 0; it < 8; ++it) {
                const int idx4 = tid + it * 256;
                const float4 v = xrow4[idx4];
                const int q  = idx4 >> 4;
                const int h0 = (idx4 & 15) << 2;
                const float f[4] = {v.x, v.y, v.z, v.w};
                #pragma unroll
                for (int j = 0; j < 4; ++j) {
                    unsigned int r; CVT_TF32(r, f[j]);
                    sXr[q * SA_STRIDE + h0 + j] = __uint_as_float(r);
                }
            }
        } else {
            const int h0 = (tid & 15) << 2;
            #pragma unroll
            for (int it = 0; it < 8; ++it) {
                const int r = (tid >> 4) + it * 16;
                const float4 v = *(const float4*)(x + (((size_t)(n * PP + r)) * PP + p) * HH + h0);
                const float f[4] = {v.x, v.y, v.z, v.w};
                #pragma unroll
                for (int j = 0; j < 4; ++j) {
                    unsigned int rr; CVT_TF32(rr, f[j]);
                    sXr[r * SA_STRIDE + h0 + j] = __uint_as_float(rr);
                }
            }
        }
        __syncthreads();

        const float* sBr = sB + pass * 64 * SB_STRIDE;

        // ---- tensor-core GEMM: 8 k-steps, 8 independent MMAs each ----
        #pragma unroll
        for (int kk = 0; kk < 8; ++kk) {
            const int ka = kk * 8 + c;
            unsigned int ar[2][4];
            #pragma unroll
            for (int mt = 0; mt < 2; ++mt) {
                const int row = m0 + 16 * mt + g;
                ar[mt][0] = __float_as_uint(sXr[row * SA_STRIDE + ka]);
                ar[mt][1] = __float_as_uint(sXr[(row + 8) * SA_STRIDE + ka]);
                ar[mt][2] = __float_as_uint(sXr[row * SA_STRIDE + ka + 4]);
                ar[mt][3] = __float_as_uint(sXr[(row + 8) * SA_STRIDE + ka + 4]);
            }
            unsigned int br0[4], br1[4];
            #pragma unroll
            for (int nt = 0; nt < 4; ++nt) {
                const int col = n0 + 8 * nt + g;
                br0[nt] = __float_as_uint(sBr[(kk * 8 + c) * SB_STRIDE + col]);
                br1[nt] = __float_as_uint(sBr[(kk * 8 + 4 + c) * SB_STRIDE + col]);
            }
            #pragma unroll
            for (int mt = 0; mt < 2; ++mt)
                #pragma unroll
                for (int nt = 0; nt < 4; ++nt)
                    MMA_TF32(acc[mt][nt], ar[mt], br0[nt], br1[nt]);
        }
    }

    // ---- epilogue ----
    const unsigned int* em = mask + (size_t)(n * PP + p) * PP;
    #pragma unroll
    for (int mt = 0; mt < 2; ++mt) {
        #pragma unroll
        for (int nt = 0; nt < 4; ++nt) {
            const int u0e = n0 + 8 * nt + 2 * c;
            const float2 fp2 = *(const float2*)(sFp + u0e);
            const float2 fd2 = *(const float2*)(sFd + u0e);
            #pragma unroll
            for (int half = 0; half < 2; ++half) {
                const int q = m0 + 16 * mt + g + 8 * half;
                const float d0 = acc[mt][nt][2 * half + 0];
                const float d1 = acc[mt][nt][2 * half + 1];
                const float2 fq2 = *(const float2*)(g_Fq + ((size_t)(n * PP + q)) * UU + u0e);
                const float msk = (em[q] != 0u) ? 1.0f : 0.0f;
                const float de = (q == p) ? 1.0f : 0.0f;
                float2 o;
                o.x = (d0 + fq2.x + fp2.x + de * fd2.x) * msk;
                o.y = (d1 + fq2.y + fp2.y + de * fd2.y) * msk;
                *(float2*)(out + (((size_t)(n * PP + p)) * PP + q) * UU + u0e) = o;
            }
        }
    }
}

// ---------------- launch ----------------
extern "C" void kernel_launch(void* const* d_in, const int* in_sizes, int n_in,
                              void* d_out, int out_size) {
    (void)in_sizes; (void)n_in; (void)out_size;
    const float*        x      = (const float*)d_in[0];
    const unsigned int* mask   = (const unsigned int*)d_in[1];
    const float*        npart  = (const float*)d_in[2];
    const float*        alpha0 = (const float*)d_in[3];
    const float*        c00    = (const float*)d_in[4];
    const float*        c01    = (const float*)d_in[5];
    const float*        c10    = (const float*)d_in[6];
    const float*        c11    = (const float*)d_in[7];
    const float*        bias   = (const float*)d_in[8];
    const float*        dbias  = (const float*)d_in[9];
    float* out = (float*)d_out;

    fuse_kernel<<<dim3(NPG, NN), 256>>>(x, npart);
    pro_kernel<<<dim3(32, NN), 256>>>(npart, alpha0, c00, c01, c10, c11, bias, dbias);

    cudaFuncSetAttribute(main_kernel, cudaFuncAttributeMaxDynamicSharedMemorySize,
                         SMEM_FLOATS * 4);
    main_kernel<<<dim3(PP, NN), 256, SMEM_FLOATS * 4>>>(x, mask, out);
}